// round 3
// baseline (speedup 1.0000x reference)
#include <cuda_runtime.h>
#include <math.h>

#define B_    128
#define H_    64
#define W_    126
#define HW_   8064          // H_*W_
#define BC_   8192          // B_*64
#define NMODE 4096          // 64*64

typedef unsigned long long u64;

__device__ __forceinline__ float lo32(u64 v) { return __uint_as_float((unsigned)v); }
__device__ __forceinline__ float hi32(u64 v) { return __uint_as_float((unsigned)(v >> 32)); }
__device__ __forceinline__ void fma2(u64& d, u64 a, u64 b) {
    asm("fma.rn.f32x2 %0, %1, %2, %0;" : "+l"(d) : "l"(a), "l"(b));
}

// ---------------- device scratch ----------------
__device__ __align__(16) float g_x  [BC_ * (size_t)HW_];   // spatial [bc][h][w]
__device__ __align__(16) float g_s1 [BC_ * (size_t)8192];  // staging A
__device__ __align__(16) float g_xf [BC_ * (size_t)8192];  // staging B
__device__ __align__(16) float g_xfm[NMODE * (size_t)16384]; // mode-major [mode][b*2+ri][i]
__device__ __align__(16) float g_wt [NMODE * (size_t)4096];  // [mode][i][o]
__device__ __align__(16) float g_fwdW[126 * 128];  // [w][n]  fwd width basis
__device__ __align__(16) float g_invW[128 * 128];  // [n][w]  inv width basis (padded)
__device__ __align__(16) float g_Gt  [128 * 128];  // [j][m]  fwd height basis^T
__device__ __align__(16) float g_G2t [128 * 128];  // [j][m]  inv height basis^T
__device__ __align__(16) float g_mw  [4096];       // effective sigmoid mask

// ---------------- basis precompute ----------------
__global__ void k_basis(const float* __restrict__ mwin) {
    int i = blockIdx.x * blockDim.x + threadIdx.x;
    const double PI2 = 6.283185307179586476925286766559;
    if (i < 126 * 128) {
        int w = i / 128, n = i % 128, k = n & 63;
        double th = PI2 * (double)(k * w) / 126.0;
        g_fwdW[i] = (n < 64) ? (float)cos(th) : (float)(-sin(th));
    }
    if (i < 128 * 128) {
        int j = i / 128, w = i % 128;
        float v = 0.f;
        if (w < 126) {
            int k = j & 63;
            double a = (k == 0 || k == 63) ? (1.0 / 126.0) : (2.0 / 126.0);
            double th = PI2 * (double)(k * w) / 126.0;
            v = (j < 64) ? (float)(a * cos(th)) : (float)(-a * sin(th));
        }
        g_invW[i] = v;
    }
    if (i < 128 * 128) {
        int j = i / 128, m = i % 128;
        int ky = m & 63, h = j & 63;
        double th = PI2 * (double)(ky * h) / 64.0;
        double c = cos(th), s = sin(th);
        g_Gt[i] = (float)((m < 64) ? ((j < 64) ? c : s) : ((j < 64) ? -s : c));
    }
    if (i < 128 * 128) {
        int j = i / 128, m = i % 128;
        int h = m & 63, ky = j & 63;
        double th = PI2 * (double)(ky * h) / 64.0;
        double c = cos(th) / 64.0, s = sin(th) / 64.0;
        g_G2t[i] = (float)((m < 64) ? ((j < 64) ? c : -s) : ((j < 64) ? s : c));
    }
    if (i < 4096) {
        int ky = i >> 6, kx = i & 63;
        float s1 = 1.f / (1.f + expf(-mwin[i]));
        if (kx == 0 || kx == 63) {
            float s2 = 1.f / (1.f + expf(-mwin[(((64 - ky) & 63) << 6) + kx]));
            s1 = 0.5f * (s1 + s2);
        }
        g_mw[i] = s1;
    }
}

// ---------------- encoder 1x1 conv 3 -> 64 ----------------
__global__ __launch_bounds__(256) void k_enc(const float* __restrict__ xin,
                                             const float* __restrict__ ew,
                                             const float* __restrict__ eb) {
    __shared__ float sx[3 * 126];
    __shared__ float sw[192];
    __shared__ float sb[64];
    int b = blockIdx.x >> 6, h = blockIdx.x & 63;
    int t = threadIdx.x;
    if (t < 192) sw[t] = ew[t];
    if (t < 64)  sb[t] = eb[t];
    for (int idx = t; idx < 378; idx += 256) {
        int j = idx / 126, w = idx % 126;
        sx[idx] = xin[(size_t)(b * 3 + j) * HW_ + h * 126 + w];
    }
    __syncthreads();
    for (int idx = t; idx < 64 * 126; idx += 256) {
        int c = idx / 126, w = idx % 126;
        float v = sb[c] + sw[c * 3] * sx[w] + sw[c * 3 + 1] * sx[126 + w]
                        + sw[c * 3 + 2] * sx[252 + w];
        g_x[(size_t)(b * 64 + c) * HW_ + h * 126 + w] = v;
    }
}

// ======================================================================
// forward width DFT (f32x2): per CTA 2 bc, C[128m x 128n] = A^T x fwdW
// As: [w(126)][m(128)+pad2]  Bs: dup'd [w(126)][2*128+pad4]
// ======================================================================
__global__ __launch_bounds__(256) void k_fwdW() {
    extern __shared__ float sm[];
    float* As = sm;              // [126][130]
    float* Bs = sm + 126 * 130;  // [126][260]
    int bcBase = blockIdx.x * 2;
    int t = threadIdx.x;
    const float* src = g_x + (size_t)bcBase * HW_;
    for (int idx = t; idx < 2 * HW_; idx += 256) {
        int half = (idx >= HW_) ? 1 : 0;
        int r = idx - half * HW_;
        int h = r / 126, w = r - h * 126;
        As[w * 130 + half * 64 + h] = src[idx];
    }
    for (int idx = t; idx < 126 * 128; idx += 256) {
        int w = idx >> 7, n = idx & 127;
        float v = g_fwdW[idx];
        *(float2*)(Bs + w * 260 + 2 * n) = make_float2(v, v);
    }
    __syncthreads();
    int ty = t >> 4, tx = t & 15;
    u64 acc[4][8];
#pragma unroll
    for (int r = 0; r < 4; r++)
#pragma unroll
        for (int c = 0; c < 8; c++) acc[r][c] = 0ull;
#pragma unroll 2
    for (int k = 0; k < 126; k++) {
        const float* ak = As + k * 130 + ty * 8;
        u64 a0 = *(const u64*)(ak);
        u64 a1 = *(const u64*)(ak + 2);
        u64 a2 = *(const u64*)(ak + 4);
        u64 a3 = *(const u64*)(ak + 6);
        const float* bk = Bs + k * 260 + tx * 16;
        ulonglong2 b0 = *(const ulonglong2*)(bk);
        ulonglong2 b1 = *(const ulonglong2*)(bk + 4);
        ulonglong2 b2 = *(const ulonglong2*)(bk + 8);
        ulonglong2 b3 = *(const ulonglong2*)(bk + 12);
        u64 bb[8] = {b0.x, b0.y, b1.x, b1.y, b2.x, b2.y, b3.x, b3.y};
        u64 aa[4] = {a0, a1, a2, a3};
#pragma unroll
        for (int r = 0; r < 4; r++)
#pragma unroll
            for (int c = 0; c < 8; c++) fma2(acc[r][c], aa[r], bb[c]);
    }
    int half = ty >> 3;
    int ri = tx >> 3;
    int kx0 = (tx * 8) & 63;
    float* dst = g_s1 + (size_t)(bcBase + half) * 8192 + ri * 4096 + kx0;
#pragma unroll
    for (int rp = 0; rp < 4; rp++) {
        int h0 = (ty * 8 + 2 * rp) & 63;
        float r0[8], r1[8];
#pragma unroll
        for (int c = 0; c < 8; c++) { r0[c] = lo32(acc[rp][c]); r1[c] = hi32(acc[rp][c]); }
        *(float4*)(dst + h0 * 64)            = make_float4(r0[0], r0[1], r0[2], r0[3]);
        *(float4*)(dst + h0 * 64 + 4)        = make_float4(r0[4], r0[5], r0[6], r0[7]);
        *(float4*)(dst + (h0 + 1) * 64)      = make_float4(r1[0], r1[1], r1[2], r1[3]);
        *(float4*)(dst + (h0 + 1) * 64 + 4)  = make_float4(r1[4], r1[5], r1[6], r1[7]);
    }
}

// ======================================================================
// height transform (f32x2): per CTA 2 bc. C[m 128][n 128] (n = 2bc x 64kx)
// As = basis^T [j][m] (direct copy), Bs dup'd [j][2*(2bc*64)]
// ======================================================================
__global__ __launch_bounds__(256) void k_hdft(int fwd) {
    extern __shared__ float sm[];
    float* As = sm;              // [128][130]
    float* Bs = sm + 128 * 130;  // [128][260]
    int bcBase = blockIdx.x * 2;
    int t = threadIdx.x;
    const float* basisT = fwd ? g_Gt : g_G2t;
    const float* in  = fwd ? g_s1 : g_xf;
    float*       out = fwd ? g_xf : g_s1;
    for (int idx = t; idx < 16384; idx += 256) {
        int j = idx >> 7, m = idx & 127;
        As[j * 130 + m] = basisT[idx];
    }
    const float* srcb = in + (size_t)bcBase * 8192;
    for (int idx = t; idx < 16384; idx += 256) {
        int half = idx >> 13, r = idx & 8191;
        int j = r >> 6, kx = r & 63;
        float v = srcb[idx];
        *(float2*)(Bs + j * 260 + half * 128 + 2 * kx) = make_float2(v, v);
    }
    __syncthreads();
    int ty = t >> 4, tx = t & 15;
    u64 acc[4][8];
#pragma unroll
    for (int r = 0; r < 4; r++)
#pragma unroll
        for (int c = 0; c < 8; c++) acc[r][c] = 0ull;
#pragma unroll 2
    for (int k = 0; k < 128; k++) {
        const float* ak = As + k * 130 + ty * 8;
        u64 aa[4];
        aa[0] = *(const u64*)(ak);     aa[1] = *(const u64*)(ak + 2);
        aa[2] = *(const u64*)(ak + 4); aa[3] = *(const u64*)(ak + 6);
        const float* bk = Bs + k * 260 + tx * 16;
        ulonglong2 b0 = *(const ulonglong2*)(bk);
        ulonglong2 b1 = *(const ulonglong2*)(bk + 4);
        ulonglong2 b2 = *(const ulonglong2*)(bk + 8);
        ulonglong2 b3 = *(const ulonglong2*)(bk + 12);
        u64 bb[8] = {b0.x, b0.y, b1.x, b1.y, b2.x, b2.y, b3.x, b3.y};
#pragma unroll
        for (int r = 0; r < 4; r++)
#pragma unroll
            for (int c = 0; c < 8; c++) fma2(acc[r][c], aa[r], bb[c]);
    }
    int half = tx >> 3;
    int kx0 = (tx * 8) & 63;
    float* dst = out + (size_t)(bcBase + half) * 8192 + kx0;
#pragma unroll
    for (int rp = 0; rp < 4; rp++) {
        int m0 = ty * 8 + 2 * rp;
        float r0[8], r1[8];
#pragma unroll
        for (int c = 0; c < 8; c++) { r0[c] = lo32(acc[rp][c]); r1[c] = hi32(acc[rp][c]); }
        if (fwd) {
            const float* w0 = g_mw + (m0 & 63) * 64 + kx0;
            const float* w1 = g_mw + ((m0 + 1) & 63) * 64 + kx0;
#pragma unroll
            for (int c = 0; c < 8; c++) { r0[c] *= w0[c]; r1[c] *= w1[c]; }
        }
        *(float4*)(dst + m0 * 64)           = make_float4(r0[0], r0[1], r0[2], r0[3]);
        *(float4*)(dst + m0 * 64 + 4)       = make_float4(r0[4], r0[5], r0[6], r0[7]);
        *(float4*)(dst + (m0 + 1) * 64)     = make_float4(r1[0], r1[1], r1[2], r1[3]);
        *(float4*)(dst + (m0 + 1) * 64 + 4) = make_float4(r1[4], r1[5], r1[6], r1[7]);
    }
}

// ---------------- transpose to mode-major ----------------
__global__ __launch_bounds__(256) void k_t1() {
    __shared__ float s[128 * 65];
    int b = blockIdx.x >> 6, ky = blockIdx.x & 63;
    int t = threadIdx.x;
    for (int idx = t; idx < 8192; idx += 256) {
        int i = idx >> 7, r = idx & 127, ri = r >> 6, kx = r & 63;
        s[(ri * 64 + i) * 65 + kx] =
            g_xf[(size_t)(b * 64 + i) * 8192 + ri * 4096 + ky * 64 + kx];
    }
    __syncthreads();
    for (int idx = t; idx < 8192; idx += 256) {
        int kx = idx >> 7, c = idx & 127;
        g_xfm[(size_t)(ky * 64 + kx) * 16384 + b * 128 + c] = s[c * 65 + kx];
    }
}

// ---------------- transpose back from mode-major ----------------
__global__ __launch_bounds__(256) void k_t2() {
    __shared__ float s[128 * 65];
    int b = blockIdx.x >> 6, ky = blockIdx.x & 63;
    int t = threadIdx.x;
    for (int idx = t; idx < 8192; idx += 256) {
        int kx = idx >> 7, c = idx & 127;
        s[c * 65 + kx] = g_s1[(size_t)(ky * 64 + kx) * 16384 + b * 128 + c];
    }
    __syncthreads();
    for (int idx = t; idx < 8192; idx += 256) {
        int o = idx >> 7, r = idx & 127, ri = r >> 6, kx = r & 63;
        g_xf[(size_t)(b * 64 + o) * 8192 + ri * 4096 + ky * 64 + kx] =
            s[(ri * 64 + o) * 65 + kx];
    }
}

// ---------------- weight fold: wt[mode][i][o] = spec[i][o][mode] + mlp[o][i] ----------------
__global__ void k_wt(const float* __restrict__ spec, const float* __restrict__ mlp) {
    __shared__ float tile[32][33];
    int x = blockIdx.x * 32 + threadIdx.x;   // mode
    int yb = blockIdx.y * 32;                // io
#pragma unroll
    for (int j = 0; j < 32; j += 8)
        tile[threadIdx.y + j][threadIdx.x] = spec[(size_t)(yb + threadIdx.y + j) * 4096 + x];
    __syncthreads();
    int io2 = yb + threadIdx.x;
    float madd = mlp[(io2 & 63) * 64 + (io2 >> 6)];
    int mb = blockIdx.x * 32;
#pragma unroll
    for (int j = 0; j < 32; j += 8)
        g_wt[(size_t)(mb + threadIdx.y + j) * 4096 + io2] =
            tile[threadIdx.x][threadIdx.y + j] + madd;
}

// ======================================================================
// per-mode GEMM (f32x2): C[256 x 64] = X[256 x 64] W[64 x 64]
// As = X^T [i(64)][row(256)+pad2], Bs dup'd [i(64)][2*64+pad4]
// threads: ty(32) x tx(8)
// ======================================================================
__global__ __launch_bounds__(256) void k_sgemm() {
    extern __shared__ float sm[];
    float* As = sm;             // [64][258]
    float* Bs = sm + 64 * 258;  // [64][132]
    int mode = blockIdx.x, t = threadIdx.x;
    const float* asrc = g_xfm + (size_t)mode * 16384;
    const float* wsrc = g_wt + (size_t)mode * 4096;
    for (int idx = t; idx < 16384; idx += 256) {
        int row = idx >> 6, i = idx & 63;
        As[i * 258 + row] = asrc[idx];
    }
    for (int idx = t; idx < 4096; idx += 256) {
        int i = idx >> 6, o = idx & 63;
        float v = wsrc[idx];
        *(float2*)(Bs + i * 132 + 2 * o) = make_float2(v, v);
    }
    __syncthreads();
    int ty = t >> 3, tx = t & 7;
    u64 acc[4][8];
#pragma unroll
    for (int r = 0; r < 4; r++)
#pragma unroll
        for (int c = 0; c < 8; c++) acc[r][c] = 0ull;
#pragma unroll 2
    for (int k = 0; k < 64; k++) {
        const float* ak = As + k * 258 + ty * 8;
        u64 aa[4];
        aa[0] = *(const u64*)(ak);     aa[1] = *(const u64*)(ak + 2);
        aa[2] = *(const u64*)(ak + 4); aa[3] = *(const u64*)(ak + 6);
        const float* bk = Bs + k * 132 + tx * 16;
        ulonglong2 b0 = *(const ulonglong2*)(bk);
        ulonglong2 b1 = *(const ulonglong2*)(bk + 4);
        ulonglong2 b2 = *(const ulonglong2*)(bk + 8);
        ulonglong2 b3 = *(const ulonglong2*)(bk + 12);
        u64 bb[8] = {b0.x, b0.y, b1.x, b1.y, b2.x, b2.y, b3.x, b3.y};
#pragma unroll
        for (int r = 0; r < 4; r++)
#pragma unroll
            for (int c = 0; c < 8; c++) fma2(acc[r][c], aa[r], bb[c]);
    }
    float* dst = g_s1 + (size_t)mode * 16384 + tx * 8;
#pragma unroll
    for (int rp = 0; rp < 4; rp++) {
        int row0 = ty * 8 + 2 * rp;
        float r0[8], r1[8];
#pragma unroll
        for (int c = 0; c < 8; c++) { r0[c] = lo32(acc[rp][c]); r1[c] = hi32(acc[rp][c]); }
        *(float4*)(dst + row0 * 64)           = make_float4(r0[0], r0[1], r0[2], r0[3]);
        *(float4*)(dst + row0 * 64 + 4)       = make_float4(r0[4], r0[5], r0[6], r0[7]);
        *(float4*)(dst + (row0 + 1) * 64)     = make_float4(r1[0], r1[1], r1[2], r1[3]);
        *(float4*)(dst + (row0 + 1) * 64 + 4) = make_float4(r1[4], r1[5], r1[6], r1[7]);
    }
}

// ======================================================================
// inverse width + bias + exact GELU (f32x2): per CTA 2 bc
// C[m 128 (2bc x 64h)][w 126] = spectrum^T x invW
// As = spectrum^T [n(128)][m(128)+pad2], Bs dup'd [n(128)][2*128]
// ======================================================================
__global__ __launch_bounds__(256) void k_inv(const float* __restrict__ sb,
                                             const float* __restrict__ mb) {
    extern __shared__ float sm[];
    float* As = sm;              // [128][130]
    float* Bs = sm + 128 * 130;  // [128][256]
    int bcBase = blockIdx.x * 2;
    int t = threadIdx.x;
    for (int idx = t; idx < 16384; idx += 256) {
        int half = idx >> 13, r = idx & 8191;
        int ri = r >> 12, h = (r >> 6) & 63, kx = r & 63;
        As[(ri * 64 + kx) * 130 + half * 64 + h] =
            g_s1[(size_t)(bcBase + half) * 8192 + r];
    }
    for (int idx = t; idx < 16384; idx += 256) {
        int n = idx >> 7, w = idx & 127;
        float v = g_invW[idx];
        *(float2*)(Bs + n * 256 + 2 * w) = make_float2(v, v);
    }
    __syncthreads();
    int ty = t >> 4, tx = t & 15;
    u64 acc[4][8];
#pragma unroll
    for (int r = 0; r < 4; r++)
#pragma unroll
        for (int c = 0; c < 8; c++) acc[r][c] = 0ull;
#pragma unroll 2
    for (int k = 0; k < 128; k++) {
        const float* ak = As + k * 130 + ty * 8;
        u64 aa[4];
        aa[0] = *(const u64*)(ak);     aa[1] = *(const u64*)(ak + 2);
        aa[2] = *(const u64*)(ak + 4); aa[3] = *(const u64*)(ak + 6);
        const float* bk = Bs + k * 256 + tx * 16;
        ulonglong2 b0 = *(const ulonglong2*)(bk);
        ulonglong2 b1 = *(const ulonglong2*)(bk + 4);
        ulonglong2 b2 = *(const ulonglong2*)(bk + 8);
        ulonglong2 b3 = *(const ulonglong2*)(bk + 12);
        u64 bb[8] = {b0.x, b0.y, b1.x, b1.y, b2.x, b2.y, b3.x, b3.y};
#pragma unroll
        for (int r = 0; r < 4; r++)
#pragma unroll
            for (int c = 0; c < 8; c++) fma2(acc[r][c], aa[r], bb[c]);
    }
    int half = ty >> 3;
    int bc = bcBase + half;
    int ch = bc & 63;
    float bias = __ldg(sb + ch) + __ldg(mb + ch);
    int w0 = tx * 8;
    float* dst = g_x + (size_t)bc * HW_;
#pragma unroll
    for (int rp = 0; rp < 4; rp++) {
        int h0 = (ty * 8 + 2 * rp) & 63;
        float rr[2][8];
#pragma unroll
        for (int c = 0; c < 8; c++) { rr[0][c] = lo32(acc[rp][c]); rr[1][c] = hi32(acc[rp][c]); }
#pragma unroll
        for (int p = 0; p < 2; p++) {
            float* row = dst + (h0 + p) * 126 + w0;
#pragma unroll
            for (int c = 0; c < 8; c += 2) {
                int w = w0 + c;
                if (w < 126) {
                    float v0 = rr[p][c] + bias;
                    float v1 = rr[p][c + 1] + bias;
                    float g0 = 0.5f * v0 * (1.0f + erff(v0 * 0.70710678118654752f));
                    float g1 = 0.5f * v1 * (1.0f + erff(v1 * 0.70710678118654752f));
                    *(float2*)(row + c) = make_float2(g0, g1);
                }
            }
        }
    }
}

// ---------------- decoder 1x1 conv 64 -> 1 ----------------
__global__ __launch_bounds__(256) void k_dec(const float* __restrict__ dw,
                                             const float* __restrict__ db,
                                             float* __restrict__ out) {
    __shared__ float sw[64];
    int b = blockIdx.x, t = threadIdx.x;
    if (t < 64) sw[t] = dw[t];
    __syncthreads();
    float bias = __ldg(db);
    for (int p = t; p < HW_; p += 256) {
        float s = bias;
        const float* base = g_x + (size_t)b * 64 * HW_ + p;
#pragma unroll 8
        for (int c = 0; c < 64; c++) s = fmaf(sw[c], base[(size_t)c * HW_], s);
        out[(size_t)b * HW_ + p] = s;
    }
}

extern "C" void kernel_launch(void* const* d_in, const int* in_sizes, int n_in,
                              void* d_out, int out_size) {
    const float* x       = (const float*)d_in[0];
    const float* mode_w  = (const float*)d_in[1];
    const float* enc_w   = (const float*)d_in[2];
    const float* enc_b   = (const float*)d_in[3];
    const float* dec_w   = (const float*)d_in[4];
    const float* dec_b   = (const float*)d_in[5];
    const float* spec_w  = (const float*)d_in[6];
    const float* spec_b  = (const float*)d_in[7];
    const float* mlp_w   = (const float*)d_in[8];
    const float* mlp_b   = (const float*)d_in[9];
    float* out = (float*)d_out;

    const int smemF = (126 * 130 + 126 * 260) * 4;  // ~196.6KB
    const int smemH = (128 * 130 + 128 * 260) * 4;  // ~199.7KB
    const int smemG = (64 * 258 + 64 * 132) * 4;    // ~99.8KB
    const int smemI = (128 * 130 + 128 * 256) * 4;  // ~197.6KB
    cudaFuncSetAttribute(k_fwdW,  cudaFuncAttributeMaxDynamicSharedMemorySize, smemF);
    cudaFuncSetAttribute(k_hdft,  cudaFuncAttributeMaxDynamicSharedMemorySize, smemH);
    cudaFuncSetAttribute(k_sgemm, cudaFuncAttributeMaxDynamicSharedMemorySize, smemG);
    cudaFuncSetAttribute(k_inv,   cudaFuncAttributeMaxDynamicSharedMemorySize, smemI);

    k_basis<<<64, 256>>>(mode_w);
    k_enc<<<8192, 256>>>(x, enc_w, enc_b);

    for (int l = 0; l < 4; l++) {
        k_wt<<<dim3(128, 128), dim3(32, 8)>>>(spec_w + (size_t)l * 16777216,
                                              mlp_w + (size_t)l * 4096);
        k_fwdW<<<4096, 256, smemF>>>();
        k_hdft<<<4096, 256, smemH>>>(1);
        k_t1<<<8192, 256>>>();
        k_sgemm<<<4096, 256, smemG>>>();
        k_t2<<<8192, 256>>>();
        k_hdft<<<4096, 256, smemH>>>(0);
        k_inv<<<4096, 256, smemI>>>(spec_b + l * 64, mlp_b + l * 64);
    }
    k_dec<<<128, 256>>>(dec_w, dec_b, out);
}